// round 2
// baseline (speedup 1.0000x reference)
#include <cuda_runtime.h>

#define N_ 20000
#define E_ 100000
#define KF 8
#define FIN 1024
#define FOUT 512
#define KTOT 1120
#define MS 32768

// ---------------- device scratch (no allocations) ----------------
__device__ float               g_f[KF * N_];
__device__ unsigned long long  g_ek[KF * E_];
__device__ int                 g_par[KF * N_];
__device__ int                 g_hk[KF * N_];
__device__ unsigned long long  g_best[KF * N_];
__device__ unsigned char       g_mark[KF * E_];
__device__ unsigned long long  g_mk[KF * MS];
__device__ int                 g_mcnt[KF];
__device__ float               g_D[KF * N_];
__device__ float               g_coord[(size_t)N_ * 96];

// ---------------- init ----------------
__global__ void k_init() {
    int i = blockIdx.x * blockDim.x + threadIdx.x;
    if (i < KF * N_) g_par[i] = i % N_;
    if (i < KF * MS) g_mk[i] = ~0ull;
    if (i < KF * E_) g_mark[i] = 0;
    if (i < KF)      g_mcnt[i] = 0;
}

// ---------------- f_all: f[k][n] = x[n] . filt_w[k] + filt_b[k] ----------------
__global__ __launch_bounds__(256) void k_fall(const float* __restrict__ x,
                                              const float* __restrict__ fw,
                                              const float* __restrict__ fb) {
    __shared__ float ws[KF][FIN];
    int tid = threadIdx.x;
    for (int i = tid; i < KF * FIN; i += 256) ws[i >> 10][i & 1023] = fw[i];
    __syncthreads();
    int warp = tid >> 5, lane = tid & 31;
    int row = blockIdx.x * 8 + warp;
    if (row >= N_) return;
    const float4* xr = (const float4*)(x + (size_t)row * FIN);
    float acc[KF];
#pragma unroll
    for (int k = 0; k < KF; k++) acc[k] = 0.f;
    for (int i = lane; i < FIN / 4; i += 32) {
        float4 xv = xr[i];
        int c = i * 4;
#pragma unroll
        for (int k = 0; k < KF; k++)
            acc[k] += xv.x * ws[k][c] + xv.y * ws[k][c + 1] +
                      xv.z * ws[k][c + 2] + xv.w * ws[k][c + 3];
    }
#pragma unroll
    for (int k = 0; k < KF; k++)
#pragma unroll
        for (int o = 16; o; o >>= 1) acc[k] += __shfl_xor_sync(0xFFFFFFFFu, acc[k], o);
    if (lane == 0) {
#pragma unroll
        for (int k = 0; k < KF; k++) g_f[k * N_ + row] = acc[k] + fb[k];
    }
}

// ---------------- edge keys: packed (ordered_max_f << 32) | edge_id ----------------
__global__ void k_ekey(const int* __restrict__ ei) {
    int i = blockIdx.x * blockDim.x + threadIdx.x;
    if (i >= KF * E_) return;
    int k = i / E_, e = i - k * E_;
    int u = ei[e], v = ei[E_ + e];
    float key = fmaxf(g_f[k * N_ + u], g_f[k * N_ + v]);
    unsigned b = __float_as_uint(key);
    b = (b & 0x80000000u) ? ~b : (b | 0x80000000u);
    g_ek[i] = ((unsigned long long)b << 32) | (unsigned)e;
}

// ---------------- Boruvka round kernels ----------------
__global__ void k_reset() {
    int i = blockIdx.x * blockDim.x + threadIdx.x;
    if (i >= KF * N_) return;
    g_best[i] = ~0ull;
    g_hk[i] = -1;
}

__global__ void k_edge(const int* __restrict__ ei) {
    int i = blockIdx.x * blockDim.x + threadIdx.x;
    if (i >= KF * E_) return;
    int k = i / E_, e = i - k * E_;
    int u = ei[e], v = ei[E_ + e];
    int cu = g_par[k * N_ + u], cv = g_par[k * N_ + v];
    if (cu != cv) {
        unsigned long long key = g_ek[i];
        atomicMin(&g_best[k * N_ + cu], key);
        atomicMin(&g_best[k * N_ + cv], key);
    }
}

__global__ void k_hook(const int* __restrict__ ei) {
    int i = blockIdx.x * blockDim.x + threadIdx.x;
    if (i >= KF * N_) return;
    int k = i / N_, n = i - k * N_;
    if (g_par[i] != n) return;           // roots only
    unsigned long long bb = g_best[i];
    if (bb == ~0ull) return;
    unsigned e = (unsigned)bb;
    int u = ei[e], v = ei[E_ + e];
    int cu = g_par[k * N_ + u], cv = g_par[k * N_ + v];
    int o = (cu == n) ? cv : cu;
    g_hk[i] = o;
    g_mark[(size_t)k * E_ + e] = 1;      // MSF edge (idempotent)
}

__global__ void k_cyc() {
    int i = blockIdx.x * blockDim.x + threadIdx.x;
    if (i >= KF * N_) return;
    int k = i / N_, n = i - k * N_;
    int o = g_hk[i];
    if (o < 0) return;
    if (g_hk[k * N_ + o] == n && n < o) return;  // break 2-cycle: smaller id stays root
    g_par[i] = o;
}

__global__ void k_flat() {
    int i = blockIdx.x * blockDim.x + threadIdx.x;
    if (i >= KF * N_) return;
    int k = i / N_;
    int p = g_par[i];
    for (;;) {
        int q = g_par[k * N_ + p];
        if (q == p) break;
        p = q;
    }
    g_par[i] = p;
}

// ---------------- gather MSF edges ----------------
__global__ void k_gather() {
    int i = blockIdx.x * blockDim.x + threadIdx.x;
    if (i >= KF * E_) return;
    if (!g_mark[i]) return;
    int k = i / E_;
    int pos = atomicAdd(&g_mcnt[k], 1);
    g_mk[(size_t)k * MS + pos] = g_ek[i];
}

// ---------------- bitonic sort of g_mk (u64 keys, per-filtration segments of MS) ----------------
__global__ __launch_bounds__(1024) void k_sloc() {
    __shared__ unsigned long long s[2048];
    unsigned blk = blockIdx.x;
    size_t base = (size_t)blk * 2048;
    unsigned lbase = (blk % (MS / 2048)) * 2048;
    s[threadIdx.x] = g_mk[base + threadIdx.x];
    s[threadIdx.x + 1024] = g_mk[base + threadIdx.x + 1024];
    __syncthreads();
    for (unsigned k2 = 2; k2 <= 2048; k2 <<= 1) {
        for (unsigned j = k2 >> 1; j > 0; j >>= 1) {
            unsigned t = threadIdx.x;
            unsigned i = 2 * t - (t & (j - 1));
            bool up = (((lbase + i) & k2) == 0);
            unsigned long long a = s[i], b = s[i + j];
            if (up ? (a > b) : (a < b)) { s[i] = b; s[i + j] = a; }
            __syncthreads();
        }
    }
    g_mk[base + threadIdx.x] = s[threadIdx.x];
    g_mk[base + threadIdx.x + 1024] = s[threadIdx.x + 1024];
}

__global__ void k_sglob(unsigned K2, unsigned j) {
    unsigned gid = blockIdx.x * blockDim.x + threadIdx.x;
    if (gid >= KF * (MS / 2)) return;
    unsigned filt = gid / (MS / 2), t = gid % (MS / 2);
    unsigned i = 2 * t - (t & (j - 1));
    unsigned l = i + j;
    unsigned long long* g = g_mk + (size_t)filt * MS;
    bool up = ((i & K2) == 0);
    unsigned long long a = g[i], b = g[l];
    if (up ? (a > b) : (a < b)) { g[i] = b; g[l] = a; }
}

__global__ __launch_bounds__(1024) void k_smerge(unsigned K2) {
    __shared__ unsigned long long s[2048];
    unsigned blk = blockIdx.x;
    size_t base = (size_t)blk * 2048;
    unsigned lbase = (blk % (MS / 2048)) * 2048;
    s[threadIdx.x] = g_mk[base + threadIdx.x];
    s[threadIdx.x + 1024] = g_mk[base + threadIdx.x + 1024];
    __syncthreads();
    for (unsigned j = 1024; j > 0; j >>= 1) {
        unsigned t = threadIdx.x;
        unsigned i = 2 * t - (t & (j - 1));
        bool up = (((lbase + i) & K2) == 0);
        unsigned long long a = s[i], b = s[i + j];
        if (up ? (a > b) : (a < b)) { s[i] = b; s[i + j] = a; }
        __syncthreads();
    }
    g_mk[base + threadIdx.x] = s[threadIdx.x];
    g_mk[base + threadIdx.x + 1024] = s[threadIdx.x + 1024];
}

// ---------------- elder-rule union-find over sorted MSF edges (1 warp / filtration) ----------------
__global__ __launch_bounds__(32) void k_uf(const int* __restrict__ ei) {
    __shared__ unsigned short spar[N_];
    __shared__ int   s_ru[32], s_rv[32];
    __shared__ float s_fu[32], s_fv[32], s_kf[32];
    int k = blockIdx.x, lane = threadIdx.x;
    const float* f = g_f + (size_t)k * N_;
    float* D = g_D + (size_t)k * N_;
    for (int i = lane; i < N_; i += 32) { spar[i] = (unsigned short)i; D[i] = f[i]; }
    __syncwarp();
    int m = g_mcnt[k];
    const unsigned long long* mk = g_mk + (size_t)k * MS;
    for (int base = 0; base < m; base += 32) {
        int i = base + lane;
        if (i < m) {
            unsigned long long kv = mk[i];
            unsigned e = (unsigned)kv;
            unsigned ob = (unsigned)(kv >> 32);
            unsigned fb2 = (ob & 0x80000000u) ? (ob & 0x7FFFFFFFu) : ~ob;
            s_kf[lane] = __uint_as_float(fb2);
            int u = ei[e], v = ei[E_ + e];
            int x = u;
            for (;;) { int p = spar[x]; if (p == x) break; int g2 = spar[p]; spar[x] = (unsigned short)g2; x = g2; }
            s_ru[lane] = x; s_fu[lane] = f[x];
            x = v;
            for (;;) { int p = spar[x]; if (p == x) break; int g2 = spar[p]; spar[x] = (unsigned short)g2; x = g2; }
            s_rv[lane] = x; s_fv[lane] = f[x];
        }
        __syncwarp();
        if (lane == 0) {
            int lim = min(32, m - base);
            for (int t = 0; t < lim; t++) {
                int x2 = s_ru[t];
                for (;;) { int p = spar[x2]; if (p == x2) break; int g2 = spar[p]; spar[x2] = (unsigned short)g2; x2 = g2; }
                int ru = x2;
                float fu = (ru == s_ru[t]) ? s_fu[t] : f[ru];
                x2 = s_rv[t];
                for (;;) { int p = spar[x2]; if (p == x2) break; int g2 = spar[p]; spar[x2] = (unsigned short)g2; x2 = g2; }
                int rv = x2;
                float fv = (rv == s_rv[t]) ? s_fv[t] : f[rv];
                if (ru != rv) {
                    if (fu <= fv) { spar[rv] = (unsigned short)ru; D[rv] = s_kf[t]; }
                    else          { spar[ru] = (unsigned short)rv; D[ru] = s_kf[t]; }
                }
            }
        }
        __syncwarp();
    }
}

// ---------------- coordinate activations ----------------
__global__ void k_act(const float* __restrict__ tri_t, const float* __restrict__ mu,
                      const float* __restrict__ sig, const float* __restrict__ lw,
                      const float* __restrict__ rc, const float* __restrict__ rr) {
    int i = blockIdx.x * blockDim.x + threadIdx.x;
    if (i >= N_ * KF) return;
    int v = i / KF, k = i - v * KF;
    float b = g_f[k * N_ + v], d = g_D[k * N_ + v];
    float s = sig[0];
    float inv = 1.f / (2.f * s * s);
    float r = fabsf(rr[0]);
    float o[12];
#pragma unroll
    for (int j = 0; j < 3; j++) o[j] = fmaxf(0.f, d - fabsf(tri_t[j] - b));
#pragma unroll
    for (int j = 0; j < 3; j++) {
        float dx = b - mu[2 * j], dy = d - mu[2 * j + 1];
        o[3 + j] = expf(-(dx * dx + dy * dy) * inv);
    }
#pragma unroll
    for (int j = 0; j < 3; j++) o[6 + j] = b * lw[2 * j] + d * lw[2 * j + 1];
#pragma unroll
    for (int j = 0; j < 3; j++) {
        float q = fabsf(b - rc[2 * j]) + fabsf(d - rc[2 * j + 1]);
        o[9 + j] = 1.f / (1.f + q) - 1.f / (1.f + fabsf(r - q));
    }
    float* dst = g_coord + (size_t)v * 96 + k * 12;
#pragma unroll
    for (int j = 0; j < 12; j++) dst[j] = o[j];
}

// ---------------- final GEMM: out[20000,512] = [x | coord] @ W^T + b ----------------
__global__ __launch_bounds__(256) void k_gemm(const float* __restrict__ x, const float* __restrict__ W,
                                              const float* __restrict__ bias, float* __restrict__ out) {
    __shared__ float As[16][132];
    __shared__ float Ws[16][68];
    int tid = threadIdx.x;
    int tn = tid & 15, tm = tid >> 4;
    int row0 = blockIdx.x * 128;
    int col0 = blockIdx.y * 64;
    float acc[8][4];
#pragma unroll
    for (int a2 = 0; a2 < 8; a2++)
#pragma unroll
        for (int b2 = 0; b2 < 4; b2++) acc[a2][b2] = 0.f;
    for (int kt = 0; kt < 70; kt++) {
        int k0 = kt * 16;
#pragma unroll
        for (int l = 0; l < 2; l++) {
            int idx = tid + l * 256;
            int r = idx >> 2, c4 = idx & 3;
            int grow = row0 + r;
            float4 vv = make_float4(0.f, 0.f, 0.f, 0.f);
            if (grow < N_) {
                if (k0 < 1024) vv = *(const float4*)(x + (size_t)grow * FIN + (k0 + c4 * 4));
                else           vv = *(const float4*)(g_coord + (size_t)grow * 96 + (k0 - 1024 + c4 * 4));
            }
            As[c4 * 4 + 0][r] = vv.x; As[c4 * 4 + 1][r] = vv.y;
            As[c4 * 4 + 2][r] = vv.z; As[c4 * 4 + 3][r] = vv.w;
        }
        {
            int r = tid >> 2, c4 = tid & 3;
            float4 vv = *(const float4*)(W + (size_t)(col0 + r) * KTOT + (k0 + c4 * 4));
            Ws[c4 * 4 + 0][r] = vv.x; Ws[c4 * 4 + 1][r] = vv.y;
            Ws[c4 * 4 + 2][r] = vv.z; Ws[c4 * 4 + 3][r] = vv.w;
        }
        __syncthreads();
#pragma unroll
        for (int kk = 0; kk < 16; kk++) {
            float4 a0 = *(const float4*)&As[kk][tm * 8];
            float4 a1 = *(const float4*)&As[kk][tm * 8 + 4];
            float4 w0 = *(const float4*)&Ws[kk][tn * 4];
            float av[8] = {a0.x, a0.y, a0.z, a0.w, a1.x, a1.y, a1.z, a1.w};
            float wv[4] = {w0.x, w0.y, w0.z, w0.w};
#pragma unroll
            for (int a2 = 0; a2 < 8; a2++)
#pragma unroll
                for (int b2 = 0; b2 < 4; b2++) acc[a2][b2] += av[a2] * wv[b2];
        }
        __syncthreads();
    }
#pragma unroll
    for (int a2 = 0; a2 < 8; a2++) {
        int r = row0 + tm * 8 + a2;
        if (r < N_) {
            int c = col0 + tn * 4;
            float4 vv = make_float4(acc[a2][0] + bias[c + 0], acc[a2][1] + bias[c + 1],
                                    acc[a2][2] + bias[c + 2], acc[a2][3] + bias[c + 3]);
            *(float4*)(out + (size_t)r * FOUT + c) = vv;
        }
    }
}

// ---------------- launcher ----------------
extern "C" void kernel_launch(void* const* d_in, const int* in_sizes, int n_in,
                              void* d_out, int out_size) {
    const float* x   = (const float*)d_in[0];
    const int*   ei  = (const int*)d_in[1];
    const float* fw  = (const float*)d_in[2];
    const float* fb  = (const float*)d_in[3];
    const float* tri = (const float*)d_in[4];
    const float* mu  = (const float*)d_in[5];
    const float* sig = (const float*)d_in[6];
    const float* lw  = (const float*)d_in[7];
    const float* rc  = (const float*)d_in[8];
    const float* rr  = (const float*)d_in[9];
    const float* W   = (const float*)d_in[10];
    const float* ob  = (const float*)d_in[11];
    float* out = (float*)d_out;

    k_init<<<(KF * E_ + 255) / 256, 256>>>();
    k_fall<<<(N_ + 7) / 8, 256>>>(x, fw, fb);
    k_ekey<<<(KF * E_ + 255) / 256, 256>>>(ei);

    for (int r = 0; r < 15; r++) {
        k_reset<<<(KF * N_ + 255) / 256, 256>>>();
        k_edge<<<(KF * E_ + 255) / 256, 256>>>(ei);
        k_hook<<<(KF * N_ + 255) / 256, 256>>>(ei);
        k_cyc<<<(KF * N_ + 255) / 256, 256>>>();
        k_flat<<<(KF * N_ + 255) / 256, 256>>>();
    }

    k_gather<<<(KF * E_ + 255) / 256, 256>>>();

    k_sloc<<<KF * (MS / 2048), 1024>>>();
    for (unsigned K2 = 4096; K2 <= MS; K2 <<= 1) {
        for (unsigned j = K2 >> 1; j >= 2048; j >>= 1)
            k_sglob<<<(KF * (MS / 2) + 255) / 256, 256>>>(K2, j);
        k_smerge<<<KF * (MS / 2048), 1024>>>(K2);
    }

    k_uf<<<KF, 32>>>(ei);
    k_act<<<(N_ * KF + 255) / 256, 256>>>(tri, mu, sig, lw, rc, rr);

    dim3 gg((N_ + 127) / 128, FOUT / 64);
    k_gemm<<<gg, 256>>>(x, W, ob, out);
}